// round 2
// baseline (speedup 1.0000x reference)
#include <cuda_runtime.h>
#include <math.h>

#define EPSV 1e-5f
#define BB   2
#define CIN  64
#define COUT 64
#define HH_  64
#define WW_  2048
#define NPIX (HH_ * WW_)      // 131072
#define BN   (BB * NPIX)      // 262144

// Softmax gate scratch: s[k][b*NPIX + n], 9 coalesced planes (9.4 MB)
__device__ float g_s[9 * BN];

// ---------------------------------------------------------------------------
// Phase 1: per-pixel 9-way softmax gates.
// logit_k = (valid && mask) ? sum_c relu(d_k . W1'_c + b1'_c) * W2_c + b2 : 0
// with BN1 folded: W1'_c = W1_c * a1_c, b1'_c = bn1_b - bn1_m * a1_c.
// ---------------------------------------------------------------------------
__global__ __launch_bounds__(256) void phase1_gates(
    const float* __restrict__ x, const int* __restrict__ mask,
    const float* __restrict__ W1, const float* __restrict__ g1,
    const float* __restrict__ b1, const float* __restrict__ m1,
    const float* __restrict__ v1, const float* __restrict__ W2,
    const float* __restrict__ b2)
{
    __shared__ float4 sW1[CIN];   // folded W1 rows
    __shared__ float2 sBW[CIN];   // (bias1_folded, W2_c)

    int tid = threadIdx.x;
    if (tid < CIN) {
        float a = g1[tid] * rsqrtf(v1[tid] + EPSV);
        sW1[tid] = make_float4(W1[tid * 4 + 0] * a, W1[tid * 4 + 1] * a,
                               W1[tid * 4 + 2] * a, W1[tid * 4 + 3] * a);
        sBW[tid] = make_float2(b1[tid] - m1[tid] * a, W2[tid]);
    }
    __syncthreads();

    int g = blockIdx.x * 256 + tid;           // 0 .. BN-1
    int b = g / NPIX;
    int n = g - b * NPIX;
    int h = n / WW_;
    int w = n - h * WW_;

    const float* xb = x + (size_t)b * (CIN + 4) * NPIX;
    const int*   mb = mask + (size_t)b * NPIX;

    float c0 = xb[0 * NPIX + n];
    float c1 = xb[1 * NPIX + n];
    float c2 = xb[2 * NPIX + n];
    float c3 = xb[3 * NPIX + n];

    float d0[9], d1[9], d2[9], d3[9];
    bool  act[9];
#pragma unroll
    for (int k = 0; k < 9; ++k) {
        int kh = k / 3 - 1, kw = k % 3 - 1;
        int hh = h + kh, ww = w + kw;
        bool valid = (hh >= 0) && (hh < HH_) && (ww >= 0) && (ww < WW_);
        int nn = valid ? (hh * WW_ + ww) : n;   // clamp to center when OOB
        act[k] = valid && (mb[nn] != 0);
        d0[k] = xb[0 * NPIX + nn] - c0;
        d1[k] = xb[1 * NPIX + nn] - c1;
        d2[k] = xb[2 * NPIX + nn] - c2;
        d3[k] = xb[3 * NPIX + nn] - c3;
    }

    float b2v = __ldg(b2);
    float lg[9];
#pragma unroll
    for (int k = 0; k < 9; ++k) lg[k] = b2v;

    for (int c = 0; c < CIN; ++c) {
        float4 wv = sW1[c];
        float2 bw = sBW[c];
#pragma unroll
        for (int k = 0; k < 9; ++k) {
            float t = fmaf(d0[k], wv.x,
                      fmaf(d1[k], wv.y,
                      fmaf(d2[k], wv.z,
                      fmaf(d3[k], wv.w, bw.x))));
            t = fmaxf(t, 0.0f);
            lg[k] = fmaf(t, bw.y, lg[k]);
        }
    }

#pragma unroll
    for (int k = 0; k < 9; ++k) lg[k] = act[k] ? lg[k] : 0.0f;

    float mx = lg[0];
#pragma unroll
    for (int k = 1; k < 9; ++k) mx = fmaxf(mx, lg[k]);
    float e[9], sum = 0.0f;
#pragma unroll
    for (int k = 0; k < 9; ++k) { e[k] = __expf(lg[k] - mx); sum += e[k]; }
    float inv = __frcp_rn(sum);
#pragma unroll
    for (int k = 0; k < 9; ++k) g_s[k * BN + g] = e[k] * inv;
}

// ---------------------------------------------------------------------------
// Phase 2: y[o](n) = BN2ReLU( sum_k s_k(n) * sum_c feat_c(n+dk) * Wagg[o, k*64+c] )
// CTA = 64 pixels (one h row segment) x all 64 outputs. 256 threads:
//   p = tid & 63 (pixel), og = tid >> 6 (16 outputs each).
// smem: feats 3x64x66 tile, per-k transposed Wagg tile WT[c][o] (stride 68),
//       gates ss[p][k].
// ---------------------------------------------------------------------------
#define FS_ELEMS (3 * CIN * 66)       // 12672
#define WT_STRIDE 68
#define WT_ELEMS (CIN * WT_STRIDE)    // 4352
#define SS_ELEMS (64 * 9)             // 576
#define SMEM_FLOATS (FS_ELEMS + WT_ELEMS + SS_ELEMS)

__global__ __launch_bounds__(256, 2) void phase2_agg(
    const float* __restrict__ x, const float* __restrict__ Wagg,
    const float* __restrict__ g2, const float* __restrict__ b2g,
    const float* __restrict__ m2, const float* __restrict__ v2,
    float* __restrict__ y)
{
    extern __shared__ float sm[];
    float* fs = sm;                    // [r][c][wl], wl in 0..65 (= w0-1 .. w0+64)
    float* WT = sm + FS_ELEMS;         // [c][o] stride 68
    float* ss = WT + WT_ELEMS;         // [p][k] stride 9

    int tid = threadIdx.x;
    int b  = blockIdx.z;
    int h  = blockIdx.y;
    int w0 = blockIdx.x * 64;

    const float* xb = x + ((size_t)b * (CIN + 4) + 4) * NPIX;

    // Load feature tile (3 rows, halo in w)
    for (int i = tid; i < FS_ELEMS; i += 256) {
        int wl = i % 66;
        int rc = i / 66;
        int c  = rc & 63;
        int r  = rc >> 6;
        int hh = h + r - 1;
        int ww = w0 + wl - 1;
        float v = 0.0f;
        if (hh >= 0 && hh < HH_ && ww >= 0 && ww < WW_)
            v = xb[(size_t)c * NPIX + hh * WW_ + ww];
        fs[i] = v;
    }
    // Load gates: ss[p*9 + k]
    for (int i = tid; i < SS_ELEMS; i += 256) {
        int k = i / 64;
        int p = i - k * 64;
        ss[p * 9 + k] = g_s[k * BN + (size_t)b * NPIX + h * WW_ + w0 + p];
    }
    __syncthreads();

    int p   = tid & 63;
    int og  = tid >> 6;
    int og16 = og * 16;

    float acc[16];
#pragma unroll
    for (int j = 0; j < 16; ++j) acc[j] = 0.0f;

    for (int k = 0; k < 9; ++k) {
        if (k) __syncthreads();  // protect previous WT reads
        // WT[c][o] = Wagg[o, k*64 + c]  (coalesced read over c)
        for (int i = tid; i < CIN * COUT; i += 256) {
            int c = i & 63;
            int o = i >> 6;
            WT[c * WT_STRIDE + o] = Wagg[(size_t)o * 576 + k * 64 + c];
        }
        __syncthreads();

        int r  = k / 3;
        int kw = k - r * 3;
        float sk = ss[p * 9 + k];
        const float* frow = &fs[(r * CIN) * 66 + (p + kw)];

#pragma unroll 4
        for (int c = 0; c < CIN; ++c) {
            float v = sk * frow[c * 66];
            const float4* wr = reinterpret_cast<const float4*>(&WT[c * WT_STRIDE + og16]);
            float4 a0 = wr[0], a1 = wr[1], a2 = wr[2], a3 = wr[3];
            acc[0]  = fmaf(v, a0.x, acc[0]);
            acc[1]  = fmaf(v, a0.y, acc[1]);
            acc[2]  = fmaf(v, a0.z, acc[2]);
            acc[3]  = fmaf(v, a0.w, acc[3]);
            acc[4]  = fmaf(v, a1.x, acc[4]);
            acc[5]  = fmaf(v, a1.y, acc[5]);
            acc[6]  = fmaf(v, a1.z, acc[6]);
            acc[7]  = fmaf(v, a1.w, acc[7]);
            acc[8]  = fmaf(v, a2.x, acc[8]);
            acc[9]  = fmaf(v, a2.y, acc[9]);
            acc[10] = fmaf(v, a2.z, acc[10]);
            acc[11] = fmaf(v, a2.w, acc[11]);
            acc[12] = fmaf(v, a3.x, acc[12]);
            acc[13] = fmaf(v, a3.y, acc[13]);
            acc[14] = fmaf(v, a3.z, acc[14]);
            acc[15] = fmaf(v, a3.w, acc[15]);
        }
    }

    // BN2 + ReLU epilogue, coalesced stores (p consecutive in warp)
    size_t base = ((size_t)b * COUT) * NPIX + (size_t)h * WW_ + w0 + p;
#pragma unroll
    for (int j = 0; j < 16; ++j) {
        int o = og16 + j;
        float a2c = __ldg(&g2[o]) * rsqrtf(__ldg(&v2[o]) + EPSV);
        float val = fmaf(acc[j] - __ldg(&m2[o]), a2c, __ldg(&b2g[o]));
        y[base + (size_t)o * NPIX] = fmaxf(val, 0.0f);
    }
}

// ---------------------------------------------------------------------------
extern "C" void kernel_launch(void* const* d_in, const int* in_sizes, int n_in,
                              void* d_out, int out_size)
{
    const float* x     = (const float*)d_in[0];
    const int*   mask  = (const int*)  d_in[1];
    const float* W1    = (const float*)d_in[2];
    const float* bn1_g = (const float*)d_in[3];
    const float* bn1_b = (const float*)d_in[4];
    const float* bn1_m = (const float*)d_in[5];
    const float* bn1_v = (const float*)d_in[6];
    const float* W2    = (const float*)d_in[7];
    const float* b2    = (const float*)d_in[8];
    const float* Wagg  = (const float*)d_in[9];
    const float* bn2_g = (const float*)d_in[10];
    const float* bn2_b = (const float*)d_in[11];
    const float* bn2_m = (const float*)d_in[12];
    const float* bn2_v = (const float*)d_in[13];
    float* y = (float*)d_out;

    static int smem_set = 0;
    if (!smem_set) {
        cudaFuncSetAttribute(phase2_agg, cudaFuncAttributeMaxDynamicSharedMemorySize,
                             SMEM_FLOATS * (int)sizeof(float));
        smem_set = 1;
    }

    phase1_gates<<<BN / 256, 256>>>(x, mask, W1, bn1_g, bn1_b, bn1_m, bn1_v, W2, b2);

    dim3 grid(WW_ / 64, HH_, BB);
    phase2_agg<<<grid, 256, SMEM_FLOATS * (int)sizeof(float)>>>(
        x, Wagg, bn2_g, bn2_b, bn2_m, bn2_v, y);
}

// round 6
// speedup vs baseline: 2.9459x; 2.9459x over previous
#include <cuda_runtime.h>
#include <cuda_fp16.h>
#include <stdint.h>
#include <math.h>

#define EPSV 1e-5f
#define BB   2
#define CIN  64
#define COUT 64
#define HH_  64
#define WW_  2048
#define NPIX (HH_ * WW_)      // 131072
#define BN   (BB * NPIX)      // 262144

// Softmax gate scratch: s[k][b*NPIX + n], 9 coalesced planes (9.4 MB)
__device__ float g_s[9 * BN];
// Pre-split, pre-swizzled Wagg tiles: per k-chunk, 64 rows (o) x 128B (64 c fp16)
__device__ __align__(16) unsigned char g_Bhi[9][8192];
__device__ __align__(16) unsigned char g_Blo[9][8192];

#define SW128(b) ((b) ^ (((b) >> 3) & 0x70))

static __device__ __forceinline__ uint32_t smem_u32(const void* p) {
    uint32_t a;
    asm("{ .reg .u64 t; cvta.to.shared.u64 t, %1; cvt.u32.u64 %0, t; }"
        : "=r"(a) : "l"(p));
    return a;
}

static __device__ __forceinline__ void ldsm4(uint32_t addr, uint32_t* r) {
    asm volatile("ldmatrix.sync.aligned.m8n8.x4.shared.b16 {%0,%1,%2,%3}, [%4];"
                 : "=r"(r[0]), "=r"(r[1]), "=r"(r[2]), "=r"(r[3]) : "r"(addr));
}

static __device__ __forceinline__ void hmma(float* c, const uint32_t* a, const uint32_t* b) {
    asm volatile("mma.sync.aligned.m16n8k16.row.col.f32.f16.f16.f32 "
                 "{%0,%1,%2,%3}, {%4,%5,%6,%7}, {%8,%9}, {%0,%1,%2,%3};"
                 : "+f"(c[0]), "+f"(c[1]), "+f"(c[2]), "+f"(c[3])
                 : "r"(a[0]), "r"(a[1]), "r"(a[2]), "r"(a[3]), "r"(b[0]), "r"(b[1]));
}

// ---------------------------------------------------------------------------
// Phase 1: per-pixel 9-way softmax gates (unchanged).
// ---------------------------------------------------------------------------
__global__ __launch_bounds__(256) void phase1_gates(
    const float* __restrict__ x, const int* __restrict__ mask,
    const float* __restrict__ W1, const float* __restrict__ g1,
    const float* __restrict__ b1, const float* __restrict__ m1,
    const float* __restrict__ v1, const float* __restrict__ W2,
    const float* __restrict__ b2)
{
    __shared__ float4 sW1[CIN];
    __shared__ float2 sBW[CIN];

    int tid = threadIdx.x;
    if (tid < CIN) {
        float a = g1[tid] * rsqrtf(v1[tid] + EPSV);
        sW1[tid] = make_float4(W1[tid * 4 + 0] * a, W1[tid * 4 + 1] * a,
                               W1[tid * 4 + 2] * a, W1[tid * 4 + 3] * a);
        sBW[tid] = make_float2(b1[tid] - m1[tid] * a, W2[tid]);
    }
    __syncthreads();

    int g = blockIdx.x * 256 + tid;
    int b = g / NPIX;
    int n = g - b * NPIX;
    int h = n / WW_;
    int w = n - h * WW_;

    const float* xb = x + (size_t)b * (CIN + 4) * NPIX;
    const int*   mb = mask + (size_t)b * NPIX;

    float c0 = xb[0 * NPIX + n];
    float c1 = xb[1 * NPIX + n];
    float c2 = xb[2 * NPIX + n];
    float c3 = xb[3 * NPIX + n];

    float d0[9], d1[9], d2[9], d3[9];
    bool  act[9];
#pragma unroll
    for (int k = 0; k < 9; ++k) {
        int kh = k / 3 - 1, kw = k % 3 - 1;
        int hh = h + kh, ww = w + kw;
        bool valid = (hh >= 0) && (hh < HH_) && (ww >= 0) && (ww < WW_);
        int nn = valid ? (hh * WW_ + ww) : n;
        act[k] = valid && (mb[nn] != 0);
        d0[k] = xb[0 * NPIX + nn] - c0;
        d1[k] = xb[1 * NPIX + nn] - c1;
        d2[k] = xb[2 * NPIX + nn] - c2;
        d3[k] = xb[3 * NPIX + nn] - c3;
    }

    float b2v = __ldg(b2);
    float lg[9];
#pragma unroll
    for (int k = 0; k < 9; ++k) lg[k] = b2v;

    for (int c = 0; c < CIN; ++c) {
        float4 wv = sW1[c];
        float2 bw = sBW[c];
#pragma unroll
        for (int k = 0; k < 9; ++k) {
            float t = fmaf(d0[k], wv.x,
                      fmaf(d1[k], wv.y,
                      fmaf(d2[k], wv.z,
                      fmaf(d3[k], wv.w, bw.x))));
            t = fmaxf(t, 0.0f);
            lg[k] = fmaf(t, bw.y, lg[k]);
        }
    }

#pragma unroll
    for (int k = 0; k < 9; ++k) lg[k] = act[k] ? lg[k] : 0.0f;

    float mx = lg[0];
#pragma unroll
    for (int k = 1; k < 9; ++k) mx = fmaxf(mx, lg[k]);
    float e[9], sum = 0.0f;
#pragma unroll
    for (int k = 0; k < 9; ++k) { e[k] = __expf(lg[k] - mx); sum += e[k]; }
    float inv = __frcp_rn(sum);
#pragma unroll
    for (int k = 0; k < 9; ++k) g_s[k * BN + g] = e[k] * inv;
}

// ---------------------------------------------------------------------------
// Prep: split Wagg into fp16 hi+lo tiles stored as SW128-swizzled smem images.
// ---------------------------------------------------------------------------
__global__ void prep_B(const float* __restrict__ Wagg)
{
    int kc = blockIdx.x;      // 0..575
    int o  = threadIdx.x;     // 0..63
    int k = kc >> 6, c = kc & 63;
    float w = Wagg[(size_t)o * 576 + kc];
    __half hi = __float2half_rn(w);
    __half lo = __float2half_rn(w - __half2float(hi));
    uint32_t off = SW128((uint32_t)(o * 128 + c * 2));
    *(__half*)(g_Bhi[k] + off) = hi;
    *(__half*)(g_Blo[k] + off) = lo;
}

// ---------------------------------------------------------------------------
// Phase 2: HMMA (mma.sync m16n8k16) GEMM. CTA = 128 px x 64 out, 8 warps,
// each warp 32x32. 3-term fp16 split, fp32 accum in registers.
// smem: A_hi[128x128B] | A_lo | B_hi[64x128B] | B_lo = 48KB, SW128 K-major.
// ---------------------------------------------------------------------------
#define SM_AHI 0
#define SM_ALO 16384
#define SM_BHI 32768
#define SM_BLO 40960
#define SM_TOTAL 49152

__global__ __launch_bounds__(256, 2) void phase2_hmma(
    const float* __restrict__ x,
    const float* __restrict__ g2, const float* __restrict__ b2g,
    const float* __restrict__ m2, const float* __restrict__ v2,
    float* __restrict__ y)
{
    extern __shared__ char sm[];
    int tid  = threadIdx.x;
    int lane = tid & 31;
    int wid  = tid >> 5;
    int b  = blockIdx.z;
    int h  = blockIdx.y;
    int w0 = blockIdx.x * 128;

    uint32_t smb = smem_u32(sm);

    int warp_m = wid & 3;          // 4 m-tiles of 32 px
    int warp_n = wid >> 2;         // 2 n-tiles of 32 out
    int pbase  = warp_m * 32;
    int obase  = warp_n * 32;

    const float* xf = x + ((size_t)b * (CIN + 4) + 4) * NPIX;

    // A-build mapping: thread -> pixel row p, channel half
    int pr  = tid & 127;
    int ch0 = (tid >> 7) * 32;
    size_t gbase = (size_t)b * NPIX + (size_t)h * WW_ + w0 + pr;

    float acc[2][4][4];
#pragma unroll
    for (int mt = 0; mt < 2; ++mt)
#pragma unroll
        for (int nt = 0; nt < 4; ++nt)
#pragma unroll
            for (int j = 0; j < 4; ++j) acc[mt][nt][j] = 0.0f;

    // Fragment ldmatrix addresses (constant across k-chunks except ks offset)
    // A: row = pbase + mt*16 + lane%16, colbyte = ks*32 + (lane>>4)*16
    uint32_t a_row  = (uint32_t)(pbase + (lane & 15));
    uint32_t a_colb = (uint32_t)((lane >> 4) * 16);
    // B: group g=lane>>3: n = obase + nt2*16 + (g>>1)*8 + (lane&7), kb=(g&1)*8
    uint32_t bg   = (uint32_t)(lane >> 3);
    uint32_t b_n  = (uint32_t)(obase + ((bg >> 1) << 3) + (lane & 7));
    uint32_t b_kb = (bg & 1) * 16;   // bytes

    for (int k = 0; k < 9; ++k) {
        // ---- build gated A_hi / A_lo ----
        int kh = k / 3 - 1, kw = k - (k / 3) * 3 - 1;
        int hh = h + kh, wwp = w0 + pr + kw;
        bool valid = (hh >= 0) && (hh < HH_) && (wwp >= 0) && (wwp < WW_);
        float sk = g_s[(size_t)k * BN + gbase];
        const float* src = xf + (size_t)hh * WW_ + wwp;
        uint32_t rowb = (uint32_t)(pr * 128);

#pragma unroll 4
        for (int c2 = 0; c2 < 16; ++c2) {
            int c = ch0 + 2 * c2;
            float f0 = valid ? __ldg(src + (size_t)c       * NPIX) : 0.0f;
            float f1 = valid ? __ldg(src + (size_t)(c + 1) * NPIX) : 0.0f;
            float v0 = sk * f0, v1 = sk * f1;
            __half2 hi2 = __floats2half2_rn(v0, v1);
            float2  hf  = __half22float2(hi2);
            __half2 lo2 = __floats2half2_rn(v0 - hf.x, v1 - hf.y);
            uint32_t off = SW128(rowb + (uint32_t)(c * 2));
            *(uint32_t*)(sm + SM_AHI + off) = *(uint32_t*)&hi2;
            *(uint32_t*)(sm + SM_ALO + off) = *(uint32_t*)&lo2;
        }

        // ---- copy pre-swizzled B_hi / B_lo for this k ----
        {
            const uint4* bh = (const uint4*)g_Bhi[k];
            const uint4* bl = (const uint4*)g_Blo[k];
            uint4* dh = (uint4*)(sm + SM_BHI);
            uint4* dl = (uint4*)(sm + SM_BLO);
#pragma unroll
            for (int i = 0; i < 2; ++i) {
                dh[tid + 256 * i] = bh[tid + 256 * i];
                dl[tid + 256 * i] = bl[tid + 256 * i];
            }
        }
        __syncthreads();

        // ---- 4 K-steps of 16; 3 split terms each ----
#pragma unroll
        for (int ks = 0; ks < 4; ++ks) {
            uint32_t ah[2][4], al[2][4], bh[2][4], bl[2][4];
#pragma unroll
            for (int mt = 0; mt < 2; ++mt) {
                uint32_t off = SW128((a_row + mt * 16) * 128 + (uint32_t)(ks * 32) + a_colb);
                ldsm4(smb + SM_AHI + off, ah[mt]);
                ldsm4(smb + SM_ALO + off, al[mt]);
            }
#pragma unroll
            for (int nt2 = 0; nt2 < 2; ++nt2) {
                uint32_t off = SW128((b_n + nt2 * 16) * 128 + (uint32_t)(ks * 32) + b_kb);
                ldsm4(smb + SM_BHI + off, bh[nt2]);
                ldsm4(smb + SM_BLO + off, bl[nt2]);
            }
#pragma unroll
            for (int mt = 0; mt < 2; ++mt) {
#pragma unroll
                for (int nt = 0; nt < 4; ++nt) {
                    const uint32_t* bfh = &bh[nt >> 1][(nt & 1) * 2];
                    const uint32_t* bfl = &bl[nt >> 1][(nt & 1) * 2];
                    hmma(acc[mt][nt], ah[mt], bfh);
                    hmma(acc[mt][nt], al[mt], bfh);
                    hmma(acc[mt][nt], ah[mt], bfl);
                }
            }
        }
        __syncthreads();
    }

    // ---- epilogue: BN2 + ReLU + store ----
    float* sc = (float*)sm;          // reuse smem: scale[64], shift[64]
    float* sh = sc + 64;
    if (tid < 64) {
        float a2 = g2[tid] * rsqrtf(v2[tid] + EPSV);
        sc[tid] = a2;
        sh[tid] = b2g[tid] - m2[tid] * a2;
    }
    __syncthreads();

    float* yb = y + ((size_t)b * COUT) * NPIX + (size_t)h * WW_ + w0;
    int rbase = pbase + (lane >> 2);
    int cbase = obase + (lane & 3) * 2;
#pragma unroll
    for (int mt = 0; mt < 2; ++mt) {
#pragma unroll
        for (int nt = 0; nt < 4; ++nt) {
            int o0 = cbase + nt * 8;
            int r0 = rbase + mt * 16;
            float s0 = sc[o0], h0 = sh[o0];
            float s1 = sc[o0 + 1], h1 = sh[o0 + 1];
            yb[(size_t)o0       * NPIX + r0]     = fmaxf(fmaf(acc[mt][nt][0], s0, h0), 0.0f);
            yb[(size_t)(o0 + 1) * NPIX + r0]     = fmaxf(fmaf(acc[mt][nt][1], s1, h1), 0.0f);
            yb[(size_t)o0       * NPIX + r0 + 8] = fmaxf(fmaf(acc[mt][nt][2], s0, h0), 0.0f);
            yb[(size_t)(o0 + 1) * NPIX + r0 + 8] = fmaxf(fmaf(acc[mt][nt][3], s1, h1), 0.0f);
        }
    }
}

// ---------------------------------------------------------------------------
extern "C" void kernel_launch(void* const* d_in, const int* in_sizes, int n_in,
                              void* d_out, int out_size)
{
    const float* x     = (const float*)d_in[0];
    const int*   mask  = (const int*)  d_in[1];
    const float* W1    = (const float*)d_in[2];
    const float* bn1_g = (const float*)d_in[3];
    const float* bn1_b = (const float*)d_in[4];
    const float* bn1_m = (const float*)d_in[5];
    const float* bn1_v = (const float*)d_in[6];
    const float* W2    = (const float*)d_in[7];
    const float* b2    = (const float*)d_in[8];
    const float* Wagg  = (const float*)d_in[9];
    const float* bn2_g = (const float*)d_in[10];
    const float* bn2_b = (const float*)d_in[11];
    const float* bn2_m = (const float*)d_in[12];
    const float* bn2_v = (const float*)d_in[13];
    float* y = (float*)d_out;

    static int smem_set = 0;
    if (!smem_set) {
        cudaFuncSetAttribute(phase2_hmma, cudaFuncAttributeMaxDynamicSharedMemorySize,
                             SM_TOTAL);
        smem_set = 1;
    }

    prep_B<<<576, 64>>>(Wagg);
    phase1_gates<<<BN / 256, 256>>>(x, mask, W1, bn1_g, bn1_b, bn1_m, bn1_v, W2, b2);

    dim3 grid(WW_ / 128, HH_, BB);
    phase2_hmma<<<grid, 256, SM_TOTAL>>>(x, bn2_g, bn2_b, bn2_m, bn2_v, y);
}

// round 7
// speedup vs baseline: 3.2120x; 1.0903x over previous
#include <cuda_runtime.h>
#include <cuda_fp16.h>
#include <stdint.h>
#include <math.h>

#define EPSV 1e-5f
#define BB   2
#define CIN  64
#define COUT 64
#define HH_  64
#define WW_  2048
#define NPIX (HH_ * WW_)      // 131072
#define BN   (BB * NPIX)      // 262144

// Softmax gate scratch: s[k][b*NPIX + n], 9 coalesced planes (9.4 MB)
__device__ float g_s[9 * BN];
// Pre-swizzled fp16 Wagg tiles: per k-chunk, 64 rows (o) x 128B (64 c fp16)
__device__ __align__(16) unsigned char g_Bhi[9][8192];

#define SW128(b) ((b) ^ (((b) >> 3) & 0x70))

static __device__ __forceinline__ uint32_t smem_u32(const void* p) {
    uint32_t a;
    asm("{ .reg .u64 t; cvta.to.shared.u64 t, %1; cvt.u32.u64 %0, t; }"
        : "=r"(a) : "l"(p));
    return a;
}

static __device__ __forceinline__ void ldsm4(uint32_t addr, uint32_t* r) {
    asm volatile("ldmatrix.sync.aligned.m8n8.x4.shared.b16 {%0,%1,%2,%3}, [%4];"
                 : "=r"(r[0]), "=r"(r[1]), "=r"(r[2]), "=r"(r[3]) : "r"(addr));
}

static __device__ __forceinline__ void hmma(float* c, const uint32_t* a, const uint32_t* b) {
    asm volatile("mma.sync.aligned.m16n8k16.row.col.f32.f16.f16.f32 "
                 "{%0,%1,%2,%3}, {%4,%5,%6,%7}, {%8,%9}, {%0,%1,%2,%3};"
                 : "+f"(c[0]), "+f"(c[1]), "+f"(c[2]), "+f"(c[3])
                 : "r"(a[0]), "r"(a[1]), "r"(a[2]), "r"(a[3]), "r"(b[0]), "r"(b[1]));
}

// ---------------------------------------------------------------------------
// Phase 1: per-pixel 9-way softmax gates (unchanged).
// ---------------------------------------------------------------------------
__global__ __launch_bounds__(256) void phase1_gates(
    const float* __restrict__ x, const int* __restrict__ mask,
    const float* __restrict__ W1, const float* __restrict__ g1,
    const float* __restrict__ b1, const float* __restrict__ m1,
    const float* __restrict__ v1, const float* __restrict__ W2,
    const float* __restrict__ b2)
{
    __shared__ float4 sW1[CIN];
    __shared__ float2 sBW[CIN];

    int tid = threadIdx.x;
    if (tid < CIN) {
        float a = g1[tid] * rsqrtf(v1[tid] + EPSV);
        sW1[tid] = make_float4(W1[tid * 4 + 0] * a, W1[tid * 4 + 1] * a,
                               W1[tid * 4 + 2] * a, W1[tid * 4 + 3] * a);
        sBW[tid] = make_float2(b1[tid] - m1[tid] * a, W2[tid]);
    }
    __syncthreads();

    int g = blockIdx.x * 256 + tid;
    int b = g / NPIX;
    int n = g - b * NPIX;
    int h = n / WW_;
    int w = n - h * WW_;

    const float* xb = x + (size_t)b * (CIN + 4) * NPIX;
    const int*   mb = mask + (size_t)b * NPIX;

    float c0 = xb[0 * NPIX + n];
    float c1 = xb[1 * NPIX + n];
    float c2 = xb[2 * NPIX + n];
    float c3 = xb[3 * NPIX + n];

    float d0[9], d1[9], d2[9], d3[9];
    bool  act[9];
#pragma unroll
    for (int k = 0; k < 9; ++k) {
        int kh = k / 3 - 1, kw = k % 3 - 1;
        int hh = h + kh, ww = w + kw;
        bool valid = (hh >= 0) && (hh < HH_) && (ww >= 0) && (ww < WW_);
        int nn = valid ? (hh * WW_ + ww) : n;
        act[k] = valid && (mb[nn] != 0);
        d0[k] = xb[0 * NPIX + nn] - c0;
        d1[k] = xb[1 * NPIX + nn] - c1;
        d2[k] = xb[2 * NPIX + nn] - c2;
        d3[k] = xb[3 * NPIX + nn] - c3;
    }

    float b2v = __ldg(b2);
    float lg[9];
#pragma unroll
    for (int k = 0; k < 9; ++k) lg[k] = b2v;

    for (int c = 0; c < CIN; ++c) {
        float4 wv = sW1[c];
        float2 bw = sBW[c];
#pragma unroll
        for (int k = 0; k < 9; ++k) {
            float t = fmaf(d0[k], wv.x,
                      fmaf(d1[k], wv.y,
                      fmaf(d2[k], wv.z,
                      fmaf(d3[k], wv.w, bw.x))));
            t = fmaxf(t, 0.0f);
            lg[k] = fmaf(t, bw.y, lg[k]);
        }
    }

#pragma unroll
    for (int k = 0; k < 9; ++k) lg[k] = act[k] ? lg[k] : 0.0f;

    float mx = lg[0];
#pragma unroll
    for (int k = 1; k < 9; ++k) mx = fmaxf(mx, lg[k]);
    float e[9], sum = 0.0f;
#pragma unroll
    for (int k = 0; k < 9; ++k) { e[k] = __expf(lg[k] - mx); sum += e[k]; }
    float inv = __frcp_rn(sum);
#pragma unroll
    for (int k = 0; k < 9; ++k) g_s[k * BN + g] = e[k] * inv;
}

// ---------------------------------------------------------------------------
// Prep: Wagg -> fp16 SW128-swizzled smem image per k-chunk.
// ---------------------------------------------------------------------------
__global__ void prep_B(const float* __restrict__ Wagg)
{
    int kc = blockIdx.x;      // 0..575
    int o  = threadIdx.x;     // 0..63
    int k = kc >> 6, c = kc & 63;
    float w = Wagg[(size_t)o * 576 + kc];
    uint32_t off = SW128((uint32_t)(o * 128 + c * 2));
    *(__half*)(g_Bhi[k] + off) = __float2half_rn(w);
}

// ---------------------------------------------------------------------------
// Phase 2: HMMA GEMM, 2-term split: (A_hi + A_lo) * B_hi, fp32 accum.
// CTA = 128 px x 64 out, 8 warps (each 32x32).
// smem: A_hi[16KB] | A_lo[16KB] | B[9][8KB] = 104KB. All 9 B chunks preloaded.
// ---------------------------------------------------------------------------
#define SM_AHI 0
#define SM_ALO 16384
#define SM_B   32768
#define SM_TOTAL (32768 + 9 * 8192)   // 106496

__global__ __launch_bounds__(256, 2) void phase2_hmma(
    const float* __restrict__ x,
    const float* __restrict__ g2, const float* __restrict__ b2g,
    const float* __restrict__ m2, const float* __restrict__ v2,
    float* __restrict__ y)
{
    extern __shared__ char sm[];
    int tid  = threadIdx.x;
    int lane = tid & 31;
    int wid  = tid >> 5;
    int b  = blockIdx.z;
    int h  = blockIdx.y;
    int w0 = blockIdx.x * 128;

    uint32_t smb = smem_u32(sm);

    int warp_m = wid & 3;          // 4 m-tiles of 32 px
    int warp_n = wid >> 2;         // 2 n-tiles of 32 out
    int pbase  = warp_m * 32;
    int obase  = warp_n * 32;

    const float* xf = x + ((size_t)b * (CIN + 4) + 4) * NPIX;

    // ---- preload all 9 B chunks (72KB) ----
    {
        const uint4* src = (const uint4*)g_Bhi;      // contiguous 9*8192 bytes
        uint4* dst = (uint4*)(sm + SM_B);
#pragma unroll
        for (int i = 0; i < 18; ++i)
            dst[tid + 256 * i] = src[tid + 256 * i];
    }

    // A-build mapping: thread -> pixel row, channel half
    int pr  = tid & 127;
    int ch0 = (tid >> 7) * 32;
    size_t gbase = (size_t)b * NPIX + (size_t)h * WW_ + w0 + pr;

    float acc[2][4][4];
#pragma unroll
    for (int mt = 0; mt < 2; ++mt)
#pragma unroll
        for (int nt = 0; nt < 4; ++nt)
#pragma unroll
            for (int j = 0; j < 4; ++j) acc[mt][nt][j] = 0.0f;

    // Fragment ldmatrix addressing
    uint32_t a_row  = (uint32_t)(pbase + (lane & 15));
    uint32_t a_colb = (uint32_t)((lane >> 4) * 16);
    uint32_t bg   = (uint32_t)(lane >> 3);
    uint32_t b_n  = (uint32_t)(obase + ((bg >> 1) << 3) + (lane & 7));
    uint32_t b_kb = (bg & 1) * 16;   // bytes

    for (int k = 0; k < 9; ++k) {
        // ---- build gated A_hi / A_lo ----
        int kh = k / 3 - 1, kw = k - (k / 3) * 3 - 1;
        int hh = h + kh, wwp = w0 + pr + kw;
        bool valid = (hh >= 0) && (hh < HH_) && (wwp >= 0) && (wwp < WW_);
        float sk = g_s[(size_t)k * BN + gbase];
        const float* src = xf + (size_t)hh * WW_ + wwp;
        uint32_t rowb = (uint32_t)(pr * 128);

#pragma unroll 4
        for (int c2 = 0; c2 < 16; ++c2) {
            int c = ch0 + 2 * c2;
            float f0 = valid ? __ldg(src + (size_t)c       * NPIX) : 0.0f;
            float f1 = valid ? __ldg(src + (size_t)(c + 1) * NPIX) : 0.0f;
            float v0 = sk * f0, v1 = sk * f1;
            __half2 hi2 = __floats2half2_rn(v0, v1);
            float2  hf  = __half22float2(hi2);
            __half2 lo2 = __floats2half2_rn(v0 - hf.x, v1 - hf.y);
            uint32_t off = SW128(rowb + (uint32_t)(c * 2));
            *(uint32_t*)(sm + SM_AHI + off) = *(uint32_t*)&hi2;
            *(uint32_t*)(sm + SM_ALO + off) = *(uint32_t*)&lo2;
        }
        __syncthreads();

        uint32_t bbase = smb + SM_B + (uint32_t)(k * 8192);

        // ---- 4 K-steps of 16; 2 split terms each ----
#pragma unroll
        for (int ks = 0; ks < 4; ++ks) {
            uint32_t ah[2][4], al[2][4], bh[2][4];
#pragma unroll
            for (int mt = 0; mt < 2; ++mt) {
                uint32_t off = SW128((a_row + mt * 16) * 128 + (uint32_t)(ks * 32) + a_colb);
                ldsm4(smb + SM_AHI + off, ah[mt]);
                ldsm4(smb + SM_ALO + off, al[mt]);
            }
#pragma unroll
            for (int nt2 = 0; nt2 < 2; ++nt2) {
                uint32_t off = SW128((b_n + nt2 * 16) * 128 + (uint32_t)(ks * 32) + b_kb);
                ldsm4(bbase + off, bh[nt2]);
            }
#pragma unroll
            for (int mt = 0; mt < 2; ++mt) {
#pragma unroll
                for (int nt = 0; nt < 4; ++nt) {
                    const uint32_t* bfh = &bh[nt >> 1][(nt & 1) * 2];
                    hmma(acc[mt][nt], ah[mt], bfh);
                    hmma(acc[mt][nt], al[mt], bfh);
                }
            }
        }
        __syncthreads();
    }

    // ---- epilogue: BN2 + ReLU + store ----
    float* sc = (float*)sm;          // reuse A region
    float* sh = sc + 64;
    if (tid < 64) {
        float a2 = g2[tid] * rsqrtf(v2[tid] + EPSV);
        sc[tid] = a2;
        sh[tid] = b2g[tid] - m2[tid] * a2;
    }
    __syncthreads();

    float* yb = y + ((size_t)b * COUT) * NPIX + (size_t)h * WW_ + w0;
    int rbase = pbase + (lane >> 2);
    int cbase = obase + (lane & 3) * 2;
#pragma unroll
    for (int mt = 0; mt < 2; ++mt) {
#pragma unroll
        for (int nt = 0; nt < 4; ++nt) {
            int o0 = cbase + nt * 8;
            int r0 = rbase + mt * 16;
            float s0 = sc[o0], h0 = sh[o0];
            float s1 = sc[o0 + 1], h1 = sh[o0 + 1];
            yb[(size_t)o0       * NPIX + r0]     = fmaxf(fmaf(acc[mt][nt][0], s0, h0), 0.0f);
            yb[(size_t)(o0 + 1) * NPIX + r0]     = fmaxf(fmaf(acc[mt][nt][1], s1, h1), 0.0f);
            yb[(size_t)o0       * NPIX + r0 + 8] = fmaxf(fmaf(acc[mt][nt][2], s0, h0), 0.0f);
            yb[(size_t)(o0 + 1) * NPIX + r0 + 8] = fmaxf(fmaf(acc[mt][nt][3], s1, h1), 0.0f);
        }
    }
}

// ---------------------------------------------------------------------------
extern "C" void kernel_launch(void* const* d_in, const int* in_sizes, int n_in,
                              void* d_out, int out_size)
{
    const float* x     = (const float*)d_in[0];
    const int*   mask  = (const int*)  d_in[1];
    const float* W1    = (const float*)d_in[2];
    const float* bn1_g = (const float*)d_in[3];
    const float* bn1_b = (const float*)d_in[4];
    const float* bn1_m = (const float*)d_in[5];
    const float* bn1_v = (const float*)d_in[6];
    const float* W2    = (const float*)d_in[7];
    const float* b2    = (const float*)d_in[8];
    const float* Wagg  = (const float*)d_in[9];
    const float* bn2_g = (const float*)d_in[10];
    const float* bn2_b = (const float*)d_in[11];
    const float* bn2_m = (const float*)d_in[12];
    const float* bn2_v = (const float*)d_in[13];
    float* y = (float*)d_out;

    static int smem_set = 0;
    if (!smem_set) {
        cudaFuncSetAttribute(phase2_hmma, cudaFuncAttributeMaxDynamicSharedMemorySize,
                             SM_TOTAL);
        smem_set = 1;
    }

    prep_B<<<576, 64>>>(Wagg);
    phase1_gates<<<BN / 256, 256>>>(x, mask, W1, bn1_g, bn1_b, bn1_m, bn1_v, W2, b2);

    dim3 grid(WW_ / 128, HH_, BB);
    phase2_hmma<<<grid, 256, SM_TOTAL>>>(x, bn2_g, bn2_b, bn2_m, bn2_v, y);
}

// round 9
// speedup vs baseline: 4.0090x; 1.2481x over previous
#include <cuda_runtime.h>
#include <cuda_fp16.h>
#include <stdint.h>
#include <math.h>

#define EPSV 1e-5f
#define BB   2
#define CIN  64
#define COUT 64
#define HH_  64
#define WW_  2048
#define NPIX (HH_ * WW_)      // 131072
#define BN   (BB * NPIX)      // 262144

// Softmax gate scratch: s[k][b*NPIX + n], 9 coalesced planes (9.4 MB)
__device__ float g_s[9 * BN];
// Pre-swizzled fp16 Wagg tiles: per k-chunk, 64 rows (o) x 128B (64 c fp16)
__device__ __align__(16) unsigned char g_Bhi[9][8192];

#define SW128(b) ((b) ^ (((b) >> 3) & 0x70))

static __device__ __forceinline__ uint32_t smem_u32(const void* p) {
    uint32_t a;
    asm("{ .reg .u64 t; cvta.to.shared.u64 t, %1; cvt.u32.u64 %0, t; }"
        : "=r"(a) : "l"(p));
    return a;
}

static __device__ __forceinline__ void ldsm4(uint32_t addr, uint32_t* r) {
    asm volatile("ldmatrix.sync.aligned.m8n8.x4.shared.b16 {%0,%1,%2,%3}, [%4];"
                 : "=r"(r[0]), "=r"(r[1]), "=r"(r[2]), "=r"(r[3]) : "r"(addr));
}

static __device__ __forceinline__ void hmma(float* c, const uint32_t* a, const uint32_t* b) {
    asm volatile("mma.sync.aligned.m16n8k16.row.col.f32.f16.f16.f32 "
                 "{%0,%1,%2,%3}, {%4,%5,%6,%7}, {%8,%9}, {%0,%1,%2,%3};"
                 : "+f"(c[0]), "+f"(c[1]), "+f"(c[2]), "+f"(c[3])
                 : "r"(a[0]), "r"(a[1]), "r"(a[2]), "r"(a[3]), "r"(b[0]), "r"(b[1]));
}

// ---------------------------------------------------------------------------
// Phase 1: per-pixel 9-way softmax gates (unchanged).
// ---------------------------------------------------------------------------
__global__ __launch_bounds__(256) void phase1_gates(
    const float* __restrict__ x, const int* __restrict__ mask,
    const float* __restrict__ W1, const float* __restrict__ g1,
    const float* __restrict__ b1, const float* __restrict__ m1,
    const float* __restrict__ v1, const float* __restrict__ W2,
    const float* __restrict__ b2)
{
    __shared__ float4 sW1[CIN];
    __shared__ float2 sBW[CIN];

    int tid = threadIdx.x;
    if (tid < CIN) {
        float a = g1[tid] * rsqrtf(v1[tid] + EPSV);
        sW1[tid] = make_float4(W1[tid * 4 + 0] * a, W1[tid * 4 + 1] * a,
                               W1[tid * 4 + 2] * a, W1[tid * 4 + 3] * a);
        sBW[tid] = make_float2(b1[tid] - m1[tid] * a, W2[tid]);
    }
    __syncthreads();

    int g = blockIdx.x * 256 + tid;
    int b = g / NPIX;
    int n = g - b * NPIX;
    int h = n / WW_;
    int w = n - h * WW_;

    const float* xb = x + (size_t)b * (CIN + 4) * NPIX;
    const int*   mb = mask + (size_t)b * NPIX;

    float c0 = xb[0 * NPIX + n];
    float c1 = xb[1 * NPIX + n];
    float c2 = xb[2 * NPIX + n];
    float c3 = xb[3 * NPIX + n];

    float d0[9], d1[9], d2[9], d3[9];
    bool  act[9];
#pragma unroll
    for (int k = 0; k < 9; ++k) {
        int kh = k / 3 - 1, kw = k % 3 - 1;
        int hh = h + kh, ww = w + kw;
        bool valid = (hh >= 0) && (hh < HH_) && (ww >= 0) && (ww < WW_);
        int nn = valid ? (hh * WW_ + ww) : n;
        act[k] = valid && (mb[nn] != 0);
        d0[k] = xb[0 * NPIX + nn] - c0;
        d1[k] = xb[1 * NPIX + nn] - c1;
        d2[k] = xb[2 * NPIX + nn] - c2;
        d3[k] = xb[3 * NPIX + nn] - c3;
    }

    float b2v = __ldg(b2);
    float lg[9];
#pragma unroll
    for (int k = 0; k < 9; ++k) lg[k] = b2v;

    for (int c = 0; c < CIN; ++c) {
        float4 wv = sW1[c];
        float2 bw = sBW[c];
#pragma unroll
        for (int k = 0; k < 9; ++k) {
            float t = fmaf(d0[k], wv.x,
                      fmaf(d1[k], wv.y,
                      fmaf(d2[k], wv.z,
                      fmaf(d3[k], wv.w, bw.x))));
            t = fmaxf(t, 0.0f);
            lg[k] = fmaf(t, bw.y, lg[k]);
        }
    }

#pragma unroll
    for (int k = 0; k < 9; ++k) lg[k] = act[k] ? lg[k] : 0.0f;

    float mx = lg[0];
#pragma unroll
    for (int k = 1; k < 9; ++k) mx = fmaxf(mx, lg[k]);
    float e[9], sum = 0.0f;
#pragma unroll
    for (int k = 0; k < 9; ++k) { e[k] = __expf(lg[k] - mx); sum += e[k]; }
    float inv = __frcp_rn(sum);
#pragma unroll
    for (int k = 0; k < 9; ++k) g_s[k * BN + g] = e[k] * inv;
}

// ---------------------------------------------------------------------------
// Prep: Wagg -> fp16 SW128-swizzled smem image per k-chunk.
// ---------------------------------------------------------------------------
__global__ void prep_B(const float* __restrict__ Wagg)
{
    int kc = blockIdx.x;      // 0..575
    int o  = threadIdx.x;     // 0..63
    int k = kc >> 6, c = kc & 63;
    float w = Wagg[(size_t)o * 576 + kc];
    uint32_t off = SW128((uint32_t)(o * 128 + c * 2));
    *(__half*)(g_Bhi[k] + off) = __float2half_rn(w);
}

// ---------------------------------------------------------------------------
// Phase 2: single-term fp16 HMMA GEMM with double-buffered A.
// CTA = 128 px x 64 out, 8 warps (each 32x32).
// smem: A0[16KB] | A1[16KB] | B[9][8KB] = 104KB; one __syncthreads per k.
// ---------------------------------------------------------------------------
#define SM_A0  0
#define SM_A1  16384
#define SM_B   32768
#define SM_TOTAL (32768 + 9 * 8192)   // 106496

__global__ __launch_bounds__(256, 2) void phase2_hmma(
    const float* __restrict__ x,
    const float* __restrict__ g2, const float* __restrict__ b2g,
    const float* __restrict__ m2, const float* __restrict__ v2,
    float* __restrict__ y)
{
    extern __shared__ char sm[];
    int tid  = threadIdx.x;
    int lane = tid & 31;
    int wid  = tid >> 5;
    int b  = blockIdx.z;
    int h  = blockIdx.y;
    int w0 = blockIdx.x * 128;

    uint32_t smb = smem_u32(sm);

    int warp_m = wid & 3;          // 4 m-tiles of 32 px
    int warp_n = wid >> 2;         // 2 n-tiles of 32 out
    int pbase  = warp_m * 32;
    int obase  = warp_n * 32;

    const float* xf = x + ((size_t)b * (CIN + 4) + 4) * NPIX;

    // ---- preload all 9 B chunks (72KB) ----
    {
        const uint4* src = (const uint4*)g_Bhi;      // contiguous 9*8192 bytes
        uint4* dst = (uint4*)(sm + SM_B);
#pragma unroll
        for (int i = 0; i < 18; ++i)
            dst[tid + 256 * i] = src[tid + 256 * i];
    }

    // A-build mapping: thread -> pixel row, channel half
    int pr  = tid & 127;
    int ch0 = (tid >> 7) * 32;
    size_t gbase = (size_t)b * NPIX + (size_t)h * WW_ + w0 + pr;
    uint32_t rowb = (uint32_t)(pr * 128);

    float acc[2][4][4];
#pragma unroll
    for (int mt = 0; mt < 2; ++mt)
#pragma unroll
        for (int nt = 0; nt < 4; ++nt)
#pragma unroll
            for (int j = 0; j < 4; ++j) acc[mt][nt][j] = 0.0f;

    // Fragment ldmatrix addressing
    uint32_t a_row  = (uint32_t)(pbase + (lane & 15));
    uint32_t a_colb = (uint32_t)((lane >> 4) * 16);
    uint32_t bg   = (uint32_t)(lane >> 3);
    uint32_t b_n  = (uint32_t)(obase + ((bg >> 1) << 3) + (lane & 7));
    uint32_t b_kb = (bg & 1) * 16;   // bytes

    // ---- build A(0) into buffer 0 ----
    {
        int hh = h - 1, wwp = w0 + pr - 1;
        bool valid = (hh >= 0) && (wwp >= 0);
        float sk = g_s[gbase];
        const float* src = xf + (size_t)hh * WW_ + wwp;
#pragma unroll 4
        for (int c2 = 0; c2 < 16; ++c2) {
            int c = ch0 + 2 * c2;
            float f0 = valid ? __ldg(src + (size_t)c       * NPIX) : 0.0f;
            float f1 = valid ? __ldg(src + (size_t)(c + 1) * NPIX) : 0.0f;
            __half2 hi2 = __floats2half2_rn(sk * f0, sk * f1);
            *(uint32_t*)(sm + SM_A0 + SW128(rowb + (uint32_t)(c * 2))) = *(uint32_t*)&hi2;
        }
    }
    __syncthreads();

    for (int k = 0; k < 9; ++k) {
        uint32_t abase = smb + ((k & 1) ? SM_A1 : SM_A0);
        uint32_t bbase = smb + SM_B + (uint32_t)(k * 8192);

        // ---- build A(k+1) into alternate buffer (LDGs issue early,
        //      latency hides under this k's ldsm+HMMA) ----
        if (k < 8) {
            int kk = k + 1;
            int kh = kk / 3 - 1, kw = kk - (kk / 3) * 3 - 1;
            int hh = h + kh, wwp = w0 + pr + kw;
            bool valid = (hh >= 0) && (hh < HH_) && (wwp >= 0) && (wwp < WW_);
            float sk = g_s[(size_t)kk * BN + gbase];
            const float* src = xf + (size_t)hh * WW_ + wwp;
            char* adst = sm + ((kk & 1) ? SM_A1 : SM_A0);
#pragma unroll 4
            for (int c2 = 0; c2 < 16; ++c2) {
                int c = ch0 + 2 * c2;
                float f0 = valid ? __ldg(src + (size_t)c       * NPIX) : 0.0f;
                float f1 = valid ? __ldg(src + (size_t)(c + 1) * NPIX) : 0.0f;
                __half2 hi2 = __floats2half2_rn(sk * f0, sk * f1);
                *(uint32_t*)(adst + SW128(rowb + (uint32_t)(c * 2))) = *(uint32_t*)&hi2;
            }
        }

        // ---- 4 K-steps of 16, single fp16 term ----
#pragma unroll
        for (int ks = 0; ks < 4; ++ks) {
            uint32_t ah[2][4], bh[2][4];
#pragma unroll
            for (int mt = 0; mt < 2; ++mt) {
                uint32_t off = SW128((a_row + mt * 16) * 128 + (uint32_t)(ks * 32) + a_colb);
                ldsm4(abase + off, ah[mt]);
            }
#pragma unroll
            for (int nt2 = 0; nt2 < 2; ++nt2) {
                uint32_t off = SW128((b_n + nt2 * 16) * 128 + (uint32_t)(ks * 32) + b_kb);
                ldsm4(bbase + off, bh[nt2]);
            }
#pragma unroll
            for (int mt = 0; mt < 2; ++mt) {
#pragma unroll
                for (int nt = 0; nt < 4; ++nt) {
                    hmma(acc[mt][nt], ah[mt], &bh[nt >> 1][(nt & 1) * 2]);
                }
            }
        }
        __syncthreads();
    }

    // ---- epilogue: BN2 + ReLU + store ----
    float* sc = (float*)sm;          // reuse A region
    float* sh = sc + 64;
    if (tid < 64) {
        float a2 = g2[tid] * rsqrtf(v2[tid] + EPSV);
        sc[tid] = a2;
        sh[tid] = b2g[tid] - m2[tid] * a2;
    }
    __syncthreads();

    float* yb = y + ((size_t)b * COUT) * NPIX + (size_t)h * WW_ + w0;
    int rbase = pbase + (lane >> 2);
    int cbase = obase + (lane & 3) * 2;
#pragma unroll
    for (int mt = 0; mt < 2; ++mt) {
#pragma unroll
        for (int nt = 0; nt < 4; ++nt) {
            int o0 = cbase + nt * 8;
            int r0 = rbase + mt * 16;
            float s0 = sc[o0], h0 = sh[o0];
            float s1 = sc[o0 + 1], h1 = sh[o0 + 1];
            yb[(size_t)o0       * NPIX + r0]     = fmaxf(fmaf(acc[mt][nt][0], s0, h0), 0.0f);
            yb[(size_t)(o0 + 1) * NPIX + r0]     = fmaxf(fmaf(acc[mt][nt][1], s1, h1), 0.0f);
            yb[(size_t)o0       * NPIX + r0 + 8] = fmaxf(fmaf(acc[mt][nt][2], s0, h0), 0.0f);
            yb[(size_t)(o0 + 1) * NPIX + r0 + 8] = fmaxf(fmaf(acc[mt][nt][3], s1, h1), 0.0f);
        }
    }
}

// ---------------------------------------------------------------------------
extern "C" void kernel_launch(void* const* d_in, const int* in_sizes, int n_in,
                              void* d_out, int out_size)
{
    const float* x     = (const float*)d_in[0];
    const int*   mask  = (const int*)  d_in[1];
    const float* W1    = (const float*)d_in[2];
    const float* bn1_g = (const float*)d_in[3];
    const float* bn1_b = (const float*)d_in[4];
    const float* bn1_m = (const float*)d_in[5];
    const float* bn1_v = (const float*)d_in[6];
    const float* W2    = (const float*)d_in[7];
    const float* b2    = (const float*)d_in[8];
    const float* Wagg  = (const float*)d_in[9];
    const float* bn2_g = (const float*)d_in[10];
    const float* bn2_b = (const float*)d_in[11];
    const float* bn2_m = (const float*)d_in[12];
    const float* bn2_v = (const float*)d_in[13];
    float* y = (float*)d_out;

    static int smem_set = 0;
    if (!smem_set) {
        cudaFuncSetAttribute(phase2_hmma, cudaFuncAttributeMaxDynamicSharedMemorySize,
                             SM_TOTAL);
        smem_set = 1;
    }

    prep_B<<<576, 64>>>(Wagg);
    phase1_gates<<<BN / 256, 256>>>(x, mask, W1, bn1_g, bn1_b, bn1_m, bn1_v, W2, b2);

    dim3 grid(WW_ / 128, HH_, BB);
    phase2_hmma<<<grid, 256, SM_TOTAL>>>(x, bn2_g, bn2_b, bn2_m, bn2_v, y);
}

// round 10
// speedup vs baseline: 5.2865x; 1.3187x over previous
#include <cuda_runtime.h>
#include <cuda_fp16.h>
#include <stdint.h>
#include <math.h>

#define EPSV 1e-5f
#define BB   2
#define CIN  64
#define COUT 64
#define HH_  64
#define WW_  2048
#define NPIX (HH_ * WW_)      // 131072
#define BN   (BB * NPIX)      // 262144

// Softmax gate scratch: s[k][b*NPIX + n], 9 coalesced planes (9.4 MB)
__device__ float g_s[9 * BN];
// Pre-swizzled fp16 Wagg tiles: per k-chunk, 64 rows (o) x 128B (64 c fp16)
__device__ __align__(16) unsigned char g_Bhi[9][8192];

#define SW128(b) ((b) ^ (((b) >> 3) & 0x70))

static __device__ __forceinline__ uint32_t smem_u32(const void* p) {
    uint32_t a;
    asm("{ .reg .u64 t; cvta.to.shared.u64 t, %1; cvt.u32.u64 %0, t; }"
        : "=r"(a) : "l"(p));
    return a;
}

static __device__ __forceinline__ void ldsm4(uint32_t addr, uint32_t* r) {
    asm volatile("ldmatrix.sync.aligned.m8n8.x4.shared.b16 {%0,%1,%2,%3}, [%4];"
                 : "=r"(r[0]), "=r"(r[1]), "=r"(r[2]), "=r"(r[3]) : "r"(addr));
}

static __device__ __forceinline__ void hmma(float* c, const uint32_t* a, const uint32_t* b) {
    asm volatile("mma.sync.aligned.m16n8k16.row.col.f32.f16.f16.f32 "
                 "{%0,%1,%2,%3}, {%4,%5,%6,%7}, {%8,%9}, {%0,%1,%2,%3};"
                 : "+f"(c[0]), "+f"(c[1]), "+f"(c[2]), "+f"(c[3])
                 : "r"(a[0]), "r"(a[1]), "r"(a[2]), "r"(a[3]), "r"(b[0]), "r"(b[1]));
}

// ---------------------------------------------------------------------------
// Phase 1: per-pixel 9-way softmax gates (unchanged).
// ---------------------------------------------------------------------------
__global__ __launch_bounds__(256) void phase1_gates(
    const float* __restrict__ x, const int* __restrict__ mask,
    const float* __restrict__ W1, const float* __restrict__ g1,
    const float* __restrict__ b1, const float* __restrict__ m1,
    const float* __restrict__ v1, const float* __restrict__ W2,
    const float* __restrict__ b2)
{
    __shared__ float4 sW1[CIN];
    __shared__ float2 sBW[CIN];

    int tid = threadIdx.x;
    if (tid < CIN) {
        float a = g1[tid] * rsqrtf(v1[tid] + EPSV);
        sW1[tid] = make_float4(W1[tid * 4 + 0] * a, W1[tid * 4 + 1] * a,
                               W1[tid * 4 + 2] * a, W1[tid * 4 + 3] * a);
        sBW[tid] = make_float2(b1[tid] - m1[tid] * a, W2[tid]);
    }
    __syncthreads();

    int g = blockIdx.x * 256 + tid;
    int b = g / NPIX;
    int n = g - b * NPIX;
    int h = n / WW_;
    int w = n - h * WW_;

    const float* xb = x + (size_t)b * (CIN + 4) * NPIX;
    const int*   mb = mask + (size_t)b * NPIX;

    float c0 = xb[0 * NPIX + n];
    float c1 = xb[1 * NPIX + n];
    float c2 = xb[2 * NPIX + n];
    float c3 = xb[3 * NPIX + n];

    float d0[9], d1[9], d2[9], d3[9];
    bool  act[9];
#pragma unroll
    for (int k = 0; k < 9; ++k) {
        int kh = k / 3 - 1, kw = k % 3 - 1;
        int hh = h + kh, ww = w + kw;
        bool valid = (hh >= 0) && (hh < HH_) && (ww >= 0) && (ww < WW_);
        int nn = valid ? (hh * WW_ + ww) : n;
        act[k] = valid && (mb[nn] != 0);
        d0[k] = xb[0 * NPIX + nn] - c0;
        d1[k] = xb[1 * NPIX + nn] - c1;
        d2[k] = xb[2 * NPIX + nn] - c2;
        d3[k] = xb[3 * NPIX + nn] - c3;
    }

    float b2v = __ldg(b2);
    float lg[9];
#pragma unroll
    for (int k = 0; k < 9; ++k) lg[k] = b2v;

    for (int c = 0; c < CIN; ++c) {
        float4 wv = sW1[c];
        float2 bw = sBW[c];
#pragma unroll
        for (int k = 0; k < 9; ++k) {
            float t = fmaf(d0[k], wv.x,
                      fmaf(d1[k], wv.y,
                      fmaf(d2[k], wv.z,
                      fmaf(d3[k], wv.w, bw.x))));
            t = fmaxf(t, 0.0f);
            lg[k] = fmaf(t, bw.y, lg[k]);
        }
    }

#pragma unroll
    for (int k = 0; k < 9; ++k) lg[k] = act[k] ? lg[k] : 0.0f;

    float mx = lg[0];
#pragma unroll
    for (int k = 1; k < 9; ++k) mx = fmaxf(mx, lg[k]);
    float e[9], sum = 0.0f;
#pragma unroll
    for (int k = 0; k < 9; ++k) { e[k] = __expf(lg[k] - mx); sum += e[k]; }
    float inv = __frcp_rn(sum);
#pragma unroll
    for (int k = 0; k < 9; ++k) g_s[k * BN + g] = e[k] * inv;
}

// ---------------------------------------------------------------------------
// Prep: Wagg -> fp16 SW128-swizzled smem image per k-chunk.
// ---------------------------------------------------------------------------
__global__ void prep_B(const float* __restrict__ Wagg)
{
    int kc = blockIdx.x;      // 0..575
    int o  = threadIdx.x;     // 0..63
    int k = kc >> 6, c = kc & 63;
    float w = Wagg[(size_t)o * 576 + kc];
    uint32_t off = SW128((uint32_t)(o * 128 + c * 2));
    *(__half*)(g_Bhi[k] + off) = __float2half_rn(w);
}

// ---------------------------------------------------------------------------
// Phase 2: feature-resident HMMA GEMM, gate folded via fp32 accumulator scale.
// CTA = 256 px x 64 out, 512 threads (16 warps: 8 m-tiles x 2 n-tiles).
// smem: feat 3 planes x 258 px x 128B (SW128) | B[9][8KB] | gates fp32[9][256].
// Mainloop: per k, ldsm A directly from feat plane (row shift = k%3, plane =
// k/3), HMMA into tmp, fold acc += s_k[row]*tmp. No syncthreads in loop.
// ---------------------------------------------------------------------------
#define PLANE   33792                 // 258*128 padded to 1024 multiple
#define SM_FEAT 0
#define SM_BW   (3 * PLANE)           // 101376
#define SM_SG   (SM_BW + 9 * 8192)    // 175104
#define SM_TOTAL (SM_SG + 9 * 256 * 4)  // 184320

__global__ __launch_bounds__(512, 1) void phase2_hmma(
    const float* __restrict__ x,
    const float* __restrict__ g2, const float* __restrict__ b2g,
    const float* __restrict__ m2, const float* __restrict__ v2,
    float* __restrict__ y)
{
    extern __shared__ char sm[];
    int tid  = threadIdx.x;
    int lane = tid & 31;
    int wid  = tid >> 5;
    int b  = blockIdx.z;
    int h  = blockIdx.y;
    int w0 = blockIdx.x * 256;

    uint32_t smb = smem_u32(sm);

    int warp_m = wid & 7;          // 8 m-tiles of 32 px
    int warp_n = wid >> 3;         // 2 n-tiles of 32 out
    int pbase  = warp_m * 32;
    int obase  = warp_n * 32;

    // ---- B copy (72KB) ----
    {
        const uint4* srcB = (const uint4*)g_Bhi;
        uint4* dstB = (uint4*)(sm + SM_BW);
#pragma unroll
        for (int i = 0; i < 9; ++i)
            dstB[tid + 512 * i] = srcB[tid + 512 * i];
    }

    // ---- gates fp32 [k][p] ----
    float* sg = (float*)(sm + SM_SG);
    {
        size_t gb = (size_t)b * NPIX + (size_t)h * WW_ + w0;
#pragma unroll
        for (int i = 0; i < 4; ++i) {
            int j = tid + 512 * i;
            sg[j] = g_s[(size_t)(j >> 8) * BN + gb + (j & 255)];
        }
        if (tid < 256) sg[2048 + tid] = g_s[(size_t)8 * BN + gb + tid];
    }

    // ---- feature tile: 3 planes x 258 pixel-rows x 64c fp16, SW128 ----
    const float* xf = x + ((size_t)b * (CIN + 4) + 4) * NPIX;
    {
        int p   = tid & 255;          // pixel column (main region)
        int ch0 = (tid >> 8) * 32;    // channel half
#pragma unroll
        for (int r = 0; r < 3; ++r) {
            int hh = h + r - 1;
            bool hv = (hh >= 0) && (hh < HH_);
            const float* rowp = xf + (size_t)hh * WW_ + w0 + p;
            char* plane = sm + SM_FEAT + r * PLANE;
            uint32_t qb = (uint32_t)((p + 1) * 128);
#pragma unroll 4
            for (int c2 = 0; c2 < 16; ++c2) {
                int c = ch0 + 2 * c2;
                float f0 = hv ? __ldg(rowp + (size_t)c       * NPIX) : 0.0f;
                float f1 = hv ? __ldg(rowp + (size_t)(c + 1) * NPIX) : 0.0f;
                __half2 v = __floats2half2_rn(f0, f1);
                *(uint32_t*)(plane + SW128(qb + (uint32_t)(c * 2))) = *(uint32_t*)&v;
            }
        }
        // halo columns q=0 (w=w0-1) and q=257 (w=w0+256)
        if (tid < 192) {
            int r    = tid / 64;
            int qsel = (tid & 63) >> 5;
            int cc   = (tid & 31) * 2;
            int q    = qsel ? 257 : 0;
            int wg   = w0 + (qsel ? 256 : -1);
            int hh   = h + r - 1;
            bool v_  = (hh >= 0) && (hh < HH_) && (wg >= 0) && (wg < WW_);
            const float* rowp = xf + (size_t)hh * WW_ + wg;
            float f0 = v_ ? __ldg(rowp + (size_t)cc       * NPIX) : 0.0f;
            float f1 = v_ ? __ldg(rowp + (size_t)(cc + 1) * NPIX) : 0.0f;
            __half2 vv = __floats2half2_rn(f0, f1);
            *(uint32_t*)(sm + SM_FEAT + r * PLANE +
                         SW128((uint32_t)(q * 128 + cc * 2))) = *(uint32_t*)&vv;
        }
    }
    __syncthreads();

    // ---- fragment addressing ----
    uint32_t aq   = (uint32_t)(pbase + (lane & 15));
    uint32_t acol = (uint32_t)((lane >> 4) * 16);
    uint32_t bg   = (uint32_t)(lane >> 3);
    uint32_t b_n  = (uint32_t)(obase + ((bg >> 1) << 3) + (lane & 7));
    uint32_t b_kb = (bg & 1) * 16;
    int srow = pbase + (lane >> 2);

    float acc[2][4][4];
#pragma unroll
    for (int mt = 0; mt < 2; ++mt)
#pragma unroll
        for (int nt = 0; nt < 4; ++nt)
#pragma unroll
            for (int j = 0; j < 4; ++j) acc[mt][nt][j] = 0.0f;

#pragma unroll
    for (int k = 0; k < 9; ++k) {
        uint32_t pl    = smb + SM_FEAT + (uint32_t)((k / 3) * PLANE);
        uint32_t qoff  = (uint32_t)(k % 3);
        uint32_t bbase = smb + SM_BW + (uint32_t)(k * 8192);

        float tmp[2][4][4];
#pragma unroll
        for (int mt = 0; mt < 2; ++mt)
#pragma unroll
            for (int nt = 0; nt < 4; ++nt)
#pragma unroll
                for (int j = 0; j < 4; ++j) tmp[mt][nt][j] = 0.0f;

#pragma unroll
        for (int ks = 0; ks < 4; ++ks) {
            uint32_t ah[2][4], bh[2][4];
#pragma unroll
            for (int mt = 0; mt < 2; ++mt) {
                uint32_t off = SW128((aq + qoff + mt * 16) * 128 +
                                     (uint32_t)(ks * 32) + acol);
                ldsm4(pl + off, ah[mt]);
            }
#pragma unroll
            for (int nt2 = 0; nt2 < 2; ++nt2) {
                uint32_t off = SW128((b_n + nt2 * 16) * 128 +
                                     (uint32_t)(ks * 32) + b_kb);
                ldsm4(bbase + off, bh[nt2]);
            }
#pragma unroll
            for (int mt = 0; mt < 2; ++mt)
#pragma unroll
                for (int nt = 0; nt < 4; ++nt)
                    hmma(tmp[mt][nt], ah[mt], &bh[nt >> 1][(nt & 1) * 2]);
        }

        // fold with fp32 gates: c0,c1 -> row srow+mt*16; c2,c3 -> +8
#pragma unroll
        for (int mt = 0; mt < 2; ++mt) {
            float s_a = sg[k * 256 + srow + mt * 16];
            float s_b = sg[k * 256 + srow + mt * 16 + 8];
#pragma unroll
            for (int nt = 0; nt < 4; ++nt) {
                acc[mt][nt][0] = fmaf(s_a, tmp[mt][nt][0], acc[mt][nt][0]);
                acc[mt][nt][1] = fmaf(s_a, tmp[mt][nt][1], acc[mt][nt][1]);
                acc[mt][nt][2] = fmaf(s_b, tmp[mt][nt][2], acc[mt][nt][2]);
                acc[mt][nt][3] = fmaf(s_b, tmp[mt][nt][3], acc[mt][nt][3]);
            }
        }
    }

    // ---- epilogue: BN2 + ReLU + store ----
    __syncthreads();
    float* sc = (float*)sm;
    float* sh = sc + 64;
    if (tid < 64) {
        float a2 = g2[tid] * rsqrtf(v2[tid] + EPSV);
        sc[tid] = a2;
        sh[tid] = b2g[tid] - m2[tid] * a2;
    }
    __syncthreads();

    float* yb = y + ((size_t)b * COUT) * NPIX + (size_t)h * WW_ + w0;
    int rbase = pbase + (lane >> 2);
    int cbase = obase + (lane & 3) * 2;
#pragma unroll
    for (int mt = 0; mt < 2; ++mt) {
#pragma unroll
        for (int nt = 0; nt < 4; ++nt) {
            int o0 = cbase + nt * 8;
            int r0 = rbase + mt * 16;
            float s0 = sc[o0], h0 = sh[o0];
            float s1 = sc[o0 + 1], h1 = sh[o0 + 1];
            yb[(size_t)o0       * NPIX + r0]     = fmaxf(fmaf(acc[mt][nt][0], s0, h0), 0.0f);
            yb[(size_t)(o0 + 1) * NPIX + r0]     = fmaxf(fmaf(acc[mt][nt][1], s1, h1), 0.0f);
            yb[(size_t)o0       * NPIX + r0 + 8] = fmaxf(fmaf(acc[mt][nt][2], s0, h0), 0.0f);
            yb[(size_t)(o0 + 1) * NPIX + r0 + 8] = fmaxf(fmaf(acc[mt][nt][3], s1, h1), 0.0f);
        }
    }
}

// ---------------------------------------------------------------------------
extern "C" void kernel_launch(void* const* d_in, const int* in_sizes, int n_in,
                              void* d_out, int out_size)
{
    const float* x     = (const float*)d_in[0];
    const int*   mask  = (const int*)  d_in[1];
    const float* W1    = (const float*)d_in[2];
    const float* bn1_g = (const float*)d_in[3];
    const float* bn1_b = (const float*)d_in[4];
    const float* bn1_m = (const float*)d_in[5];
    const float* bn1_v = (const float*)d_in[6];
    const float* W2    = (const float*)d_in[7];
    const float* b2    = (const float*)d_in[8];
    const float* Wagg  = (const float*)d_in[9];
    const float* bn2_g = (const float*)d_in[10];
    const float* bn2_b = (const float*)d_in[11];
    const float* bn2_m = (const float*)d_in[12];
    const float* bn2_v = (const float*)d_in[13];
    float* y = (float*)d_out;

    static int smem_set = 0;
    if (!smem_set) {
        cudaFuncSetAttribute(phase2_hmma, cudaFuncAttributeMaxDynamicSharedMemorySize,
                             SM_TOTAL);
        smem_set = 1;
    }

    prep_B<<<576, 64>>>(Wagg);
    phase1_gates<<<BN / 256, 256>>>(x, mask, W1, bn1_g, bn1_b, bn1_m, bn1_v, W2, b2);

    dim3 grid(WW_ / 256, HH_, BB);
    phase2_hmma<<<grid, 512, SM_TOTAL>>>(x, bn2_g, bn2_b, bn2_m, bn2_v, y);
}